// round 1
// baseline (speedup 1.0000x reference)
#include <cuda_runtime.h>
#include <math.h>

#define NN   50000
#define EE   500000
#define DIN  128
#define HH   256
#define PP   100000

// ---------------- scratch (static device globals; no runtime alloc) --------
__device__ float g_h   [NN * HH];   // GEMM output / pre-aggregation buffer
__device__ float g_embL[NN * HH];   // left-side embeddings
__device__ float g_embR[NN * HH];   // right-side embeddings
__device__ int   g_deg   [2][NN];
__device__ float g_dinv  [2][NN];
__device__ int   g_rowptr[2][NN + 1];
__device__ int   g_wptr  [2][NN];
__device__ int   g_csr   [2][EE];

// ---------------- CSR build ------------------------------------------------
__global__ void k_init_deg(int* deg) {
    int i = blockIdx.x * blockDim.x + threadIdx.x;
    if (i < NN) deg[i] = 1;                 // self-loop
}

__global__ void k_count(const int* __restrict__ ei, int* __restrict__ deg) {
    int e = blockIdx.x * blockDim.x + threadIdx.x;
    if (e < EE) atomicAdd(&deg[ei[EE + e]], 1);   // dst row of edge_index
}

__global__ void k_dinv(const int* __restrict__ deg, float* __restrict__ dinv) {
    int i = blockIdx.x * blockDim.x + threadIdx.x;
    if (i < NN) dinv[i] = rsqrtf((float)deg[i]);
}

// one-block exclusive scan of (deg[i]-1) -> rowptr, wptr
__global__ void k_scan(const int* __restrict__ deg, int* __restrict__ rowptr,
                       int* __restrict__ wptr) {
    __shared__ int ssum[1024];
    int t = threadIdx.x;
    const int chunk = (NN + 1023) / 1024;
    int lo = t * chunk;
    int hi = lo + chunk; if (hi > NN) hi = NN; if (lo > NN) lo = NN;
    int s = 0;
    for (int i = lo; i < hi; i++) s += deg[i] - 1;
    ssum[t] = s;
    __syncthreads();
    // Hillis-Steele inclusive scan
    for (int off = 1; off < 1024; off <<= 1) {
        int v = (t >= off) ? ssum[t - off] : 0;
        __syncthreads();
        ssum[t] += v;
        __syncthreads();
    }
    int run = (t == 0) ? 0 : ssum[t - 1];
    for (int i = lo; i < hi; i++) {
        rowptr[i] = run;
        wptr[i]   = run;
        run += deg[i] - 1;
    }
    if (t == 1023) rowptr[NN] = run;   // == EE
}

__global__ void k_fill(const int* __restrict__ ei, int* __restrict__ wptr,
                       int* __restrict__ csr) {
    int e = blockIdx.x * blockDim.x + threadIdx.x;
    if (e < EE) {
        int dst = ei[EE + e];
        int p = atomicAdd(&wptr[dst], 1);
        csr[p] = ei[e];                 // src
    }
}

// ---------------- SGEMM: C[M,256] = A[M,K] @ B[K,256] ----------------------
// 64x64 tile, 256 threads, 4x4 per thread, K-tile 16.
__global__ __launch_bounds__(256, 2)
void k_gemm(const float* __restrict__ A, const float* __restrict__ B,
            float* __restrict__ C, int M, int K) {
    __shared__ float As[64][17];
    __shared__ float Bs[16][64];
    int tid = threadIdx.x;
    int tx = tid & 15, ty = tid >> 4;
    int rb = blockIdx.x * 64, cb = blockIdx.y * 64;

    float4 acc[4];
    #pragma unroll
    for (int i = 0; i < 4; i++) acc[i] = make_float4(0.f, 0.f, 0.f, 0.f);

    int lr  = tid >> 2;          // A-load row 0..63
    int lq  = (tid & 3) * 4;     // A-load k offset (float4)
    int bkk = tid >> 4;          // B-load k 0..15
    int bc  = (tid & 15) * 4;    // B-load col offset

    for (int k0 = 0; k0 < K; k0 += 16) {
        int ar = rb + lr;
        float4 av = (ar < M) ? *(const float4*)(A + (size_t)ar * K + k0 + lq)
                             : make_float4(0.f, 0.f, 0.f, 0.f);
        As[lr][lq + 0] = av.x; As[lr][lq + 1] = av.y;
        As[lr][lq + 2] = av.z; As[lr][lq + 3] = av.w;
        *(float4*)&Bs[bkk][bc] =
            *(const float4*)(B + (size_t)(k0 + bkk) * HH + cb + bc);
        __syncthreads();
        #pragma unroll
        for (int kk = 0; kk < 16; kk++) {
            float4 b = *(float4*)&Bs[kk][tx * 4];
            #pragma unroll
            for (int i = 0; i < 4; i++) {
                float a = As[ty * 4 + i][kk];
                acc[i].x += a * b.x; acc[i].y += a * b.y;
                acc[i].z += a * b.z; acc[i].w += a * b.w;
            }
        }
        __syncthreads();
    }
    #pragma unroll
    for (int i = 0; i < 4; i++) {
        int r = rb + ty * 4 + i;
        if (r < M) *(float4*)(C + (size_t)r * HH + cb + tx * 4) = acc[i];
    }
}

// ---------------- aggregation: out = relu(D^-1/2 A D^-1/2 h + b) -----------
// blockDim (64,4): 64 threads per node (4 cols each via float4), 4 nodes/block
__global__ __launch_bounds__(256, 4)
void k_agg(const float* __restrict__ h, const int* __restrict__ rowptr,
           const int* __restrict__ csr, const float* __restrict__ dinv,
           const float* __restrict__ bias, float* __restrict__ out) {
    int node = blockIdx.x * 4 + threadIdx.y;
    if (node >= NN) return;
    int c = threadIdx.x * 4;
    float di = dinv[node];

    float4 v = *(const float4*)(h + (size_t)node * HH + c);
    float w0 = di * di;
    float4 acc = make_float4(v.x * w0, v.y * w0, v.z * w0, v.w * w0);

    int lo = rowptr[node], hi = rowptr[node + 1];
    for (int e = lo; e < hi; e++) {
        int s = csr[e];
        float w = di * dinv[s];
        float4 u = *(const float4*)(h + (size_t)s * HH + c);
        acc.x += w * u.x; acc.y += w * u.y;
        acc.z += w * u.z; acc.w += w * u.w;
    }
    float4 b = *(const float4*)(bias + c);
    acc.x = fmaxf(acc.x + b.x, 0.f);
    acc.y = fmaxf(acc.y + b.y, 0.f);
    acc.z = fmaxf(acc.z + b.z, 0.f);
    acc.w = fmaxf(acc.w + b.w, 0.f);
    *(float4*)(out + (size_t)node * HH + c) = acc;
}

// ---------------- fused pair MLP: gather+concat -> fc1+relu -> fc2 -> sigmoid
// block = 256 threads (8 warps), 32 pairs/block (4 pairs/warp), K=512
__global__ __launch_bounds__(256, 2)
void k_fc(const float* __restrict__ embL, const float* __restrict__ embR,
          const int* __restrict__ y,
          const float* __restrict__ fcW, const float* __restrict__ fcb,
          const float* __restrict__ fc2W, const float* __restrict__ fc2b,
          float* __restrict__ out) {
    __shared__ float As[32][36];     // 36: 16B-aligned rows, no read conflicts
    __shared__ float Bs[32][256];
    __shared__ int sy0[32], sy1[32];

    int tid = threadIdx.x;
    int pbase = blockIdx.x * 32;
    if (tid < 32) {
        sy0[tid] = y[(pbase + tid) * 2 + 0];
        sy1[tid] = y[(pbase + tid) * 2 + 1];
    }
    __syncthreads();

    int w = tid >> 5, lane = tid & 31;
    float acc[4][8];
    #pragma unroll
    for (int p = 0; p < 4; p++)
        #pragma unroll
        for (int j = 0; j < 8; j++) acc[p][j] = 0.f;

    int ap = tid >> 3;          // A-gather pair 0..31
    int aq = (tid & 7) * 4;     // A-gather k offset within 32-tile

    for (int kt = 0; kt < 2 * HH; kt += 32) {
        // gather A: first 256 k from embL[y0], last 256 from embR[y1]
        {
            int kg = kt + aq;
            const float* base = (kg < HH)
                ? (embL + (size_t)sy0[ap] * HH + kg)
                : (embR + (size_t)sy1[ap] * HH + (kg - HH));
            *(float4*)&As[ap][aq] = *(const float4*)base;
        }
        // load B tile: fcW[kt..kt+32, 0..256)
        #pragma unroll
        for (int i = 0; i < 8; i++) {
            int idx = tid + i * 256;
            int kk = idx >> 6, cc = (idx & 63) * 4;
            *(float4*)&Bs[kk][cc] =
                *(const float4*)(fcW + (size_t)(kt + kk) * HH + cc);
        }
        __syncthreads();
        #pragma unroll
        for (int kk = 0; kk < 32; kk++) {
            float4 b0 = *(float4*)&Bs[kk][lane * 8];
            float4 b1 = *(float4*)&Bs[kk][lane * 8 + 4];
            #pragma unroll
            for (int pp = 0; pp < 4; pp++) {
                float a = As[w * 4 + pp][kk];
                acc[pp][0] += a * b0.x; acc[pp][1] += a * b0.y;
                acc[pp][2] += a * b0.z; acc[pp][3] += a * b0.w;
                acc[pp][4] += a * b1.x; acc[pp][5] += a * b1.y;
                acc[pp][6] += a * b1.z; acc[pp][7] += a * b1.w;
            }
        }
        __syncthreads();
    }

    // epilogue: relu + fc2 dot + sigmoid
    float fb[8], fw[8];
    #pragma unroll
    for (int j = 0; j < 8; j++) {
        fb[j] = fcb [lane * 8 + j];
        fw[j] = fc2W[lane * 8 + j];
    }
    float bias2 = fc2b[0];
    #pragma unroll
    for (int pp = 0; pp < 4; pp++) {
        float s = 0.f;
        #pragma unroll
        for (int j = 0; j < 8; j++) {
            float hv = acc[pp][j] + fb[j];
            hv = hv > 0.f ? hv : 0.f;
            s += hv * fw[j];
        }
        #pragma unroll
        for (int off = 16; off > 0; off >>= 1)
            s += __shfl_xor_sync(0xffffffffu, s, off);
        if (lane == 0) {
            int pi = pbase + w * 4 + pp;
            out[pi] = 1.f / (1.f + expf(-(s + bias2)));
        }
    }
}

// ---------------- launch ---------------------------------------------------
extern "C" void kernel_launch(void* const* d_in, const int* in_sizes, int n_in,
                              void* d_out, int out_size) {
    const float* x_s  = (const float*)d_in[0];
    const float* x_t  = (const float*)d_in[1];
    const int*   ei_s = (const int*)  d_in[2];
    const int*   ei_t = (const int*)  d_in[3];
    const int*   y    = (const int*)  d_in[4];
    const float* W1   = (const float*)d_in[5];
    const float* b1   = (const float*)d_in[6];
    const float* W2   = (const float*)d_in[7];
    const float* b2   = (const float*)d_in[8];
    const float* fcW  = (const float*)d_in[9];
    const float* fcb  = (const float*)d_in[10];
    const float* fc2W = (const float*)d_in[11];
    const float* fc2b = (const float*)d_in[12];
    float* out = (float*)d_out;

    float *h, *embL, *embR, *dinvp;
    int *degp, *rowp, *wp, *csrp;
    cudaGetSymbolAddress((void**)&h,     g_h);
    cudaGetSymbolAddress((void**)&embL,  g_embL);
    cudaGetSymbolAddress((void**)&embR,  g_embR);
    cudaGetSymbolAddress((void**)&degp,  g_deg);
    cudaGetSymbolAddress((void**)&dinvp, g_dinv);
    cudaGetSymbolAddress((void**)&rowp,  g_rowptr);
    cudaGetSymbolAddress((void**)&wp,    g_wptr);
    cudaGetSymbolAddress((void**)&csrp,  g_csr);

    const int* ei[2]  = { ei_s, ei_t };
    int nb_n = (NN + 255) / 256;
    int nb_e = (EE + 255) / 256;

    for (int side = 0; side < 2; side++) {
        int*   deg = degp  + side * NN;
        float* dv  = dinvp + side * NN;
        int*   rp  = rowp  + side * (NN + 1);
        int*   wpt = wp    + side * NN;
        int*   cs  = csrp  + side * EE;
        k_init_deg<<<nb_n, 256>>>(deg);
        k_count  <<<nb_e, 256>>>(ei[side], deg);
        k_dinv   <<<nb_n, 256>>>(deg, dv);
        k_scan   <<<1, 1024>>>(deg, rp, wpt);
        k_fill   <<<nb_e, 256>>>(ei[side], wpt, cs);
    }

    dim3 ggrid((NN + 63) / 64, HH / 64);
    int agrid = (NN + 3) / 4;
    dim3 ablk(64, 4);

    // left side (x_s, graph s)
    k_gemm<<<ggrid, 256>>>(x_s, W1, h, NN, DIN);
    k_agg <<<agrid, ablk>>>(h, rowp, csrp, dinvp, b1, embL);
    k_gemm<<<ggrid, 256>>>(embL, W2, h, NN, HH);
    k_agg <<<agrid, ablk>>>(h, rowp, csrp, dinvp, b2, embL);

    // right side (x_t, graph t)
    k_gemm<<<ggrid, 256>>>(x_t, W1, h, NN, DIN);
    k_agg <<<agrid, ablk>>>(h, rowp + (NN + 1), csrp + EE, dinvp + NN, b1, embR);
    k_gemm<<<ggrid, 256>>>(embR, W2, h, NN, HH);
    k_agg <<<agrid, ablk>>>(h, rowp + (NN + 1), csrp + EE, dinvp + NN, b2, embR);

    // fused pair MLP
    k_fc<<<PP / 32, 256>>>(embL, embR, y, fcW, fcb, fc2W, fc2b, out);
}

// round 2
// speedup vs baseline: 1.0031x; 1.0031x over previous
#include <cuda_runtime.h>
#include <math.h>

#define NN   50000
#define EE   500000
#define DIN  128
#define HH   256
#define PP   100000

// ---------------- scratch (static device globals; no runtime alloc) --------
__device__ float g_h   [NN * HH];   // GEMM output / pre-aggregation buffer
__device__ float g_embL[NN * HH];   // left-side embeddings
__device__ float g_embR[NN * HH];   // right-side embeddings
__device__ int   g_deg   [2][NN];
__device__ float g_dinv  [2][NN];
__device__ int   g_rowptr[2][NN + 1];
__device__ int   g_wptr  [2][NN];
__device__ int   g_csr   [2][EE];

// ---------------- CSR build ------------------------------------------------
__global__ void k_init_deg(int* deg) {
    int i = blockIdx.x * blockDim.x + threadIdx.x;
    if (i < NN) deg[i] = 1;                 // self-loop
}

__global__ void k_count(const int* __restrict__ ei, int* __restrict__ deg) {
    int e = blockIdx.x * blockDim.x + threadIdx.x;
    if (e < EE) atomicAdd(&deg[ei[EE + e]], 1);   // dst row of edge_index
}

__global__ void k_dinv(const int* __restrict__ deg, float* __restrict__ dinv) {
    int i = blockIdx.x * blockDim.x + threadIdx.x;
    if (i < NN) dinv[i] = rsqrtf((float)deg[i]);
}

// one-block exclusive scan of (deg[i]-1) -> rowptr, wptr
__global__ void k_scan(const int* __restrict__ deg, int* __restrict__ rowptr,
                       int* __restrict__ wptr) {
    __shared__ int ssum[1024];
    int t = threadIdx.x;
    const int chunk = (NN + 1023) / 1024;
    int lo = t * chunk;
    int hi = lo + chunk; if (hi > NN) hi = NN; if (lo > NN) lo = NN;
    int s = 0;
    for (int i = lo; i < hi; i++) s += deg[i] - 1;
    ssum[t] = s;
    __syncthreads();
    // Hillis-Steele inclusive scan
    for (int off = 1; off < 1024; off <<= 1) {
        int v = (t >= off) ? ssum[t - off] : 0;
        __syncthreads();
        ssum[t] += v;
        __syncthreads();
    }
    int run = (t == 0) ? 0 : ssum[t - 1];
    for (int i = lo; i < hi; i++) {
        rowptr[i] = run;
        wptr[i]   = run;
        run += deg[i] - 1;
    }
    if (t == 1023) rowptr[NN] = run;   // == EE
}

__global__ void k_fill(const int* __restrict__ ei, int* __restrict__ wptr,
                       int* __restrict__ csr) {
    int e = blockIdx.x * blockDim.x + threadIdx.x;
    if (e < EE) {
        int dst = ei[EE + e];
        int p = atomicAdd(&wptr[dst], 1);
        csr[p] = ei[e];                 // src
    }
}

// ---------------- SGEMM: C[M,256] = A[M,K] @ B[K,256] ----------------------
// 64x64 tile, 256 threads, 4x4 per thread, K-tile 16.
__global__ __launch_bounds__(256, 2)
void k_gemm(const float* __restrict__ A, const float* __restrict__ B,
            float* __restrict__ C, int M, int K) {
    __shared__ float As[64][17];
    __shared__ float Bs[16][64];
    int tid = threadIdx.x;
    int tx = tid & 15, ty = tid >> 4;
    int rb = blockIdx.x * 64, cb = blockIdx.y * 64;

    float4 acc[4];
    #pragma unroll
    for (int i = 0; i < 4; i++) acc[i] = make_float4(0.f, 0.f, 0.f, 0.f);

    int lr  = tid >> 2;          // A-load row 0..63
    int lq  = (tid & 3) * 4;     // A-load k offset (float4)
    int bkk = tid >> 4;          // B-load k 0..15
    int bc  = (tid & 15) * 4;    // B-load col offset

    for (int k0 = 0; k0 < K; k0 += 16) {
        int ar = rb + lr;
        float4 av = (ar < M) ? *(const float4*)(A + (size_t)ar * K + k0 + lq)
                             : make_float4(0.f, 0.f, 0.f, 0.f);
        As[lr][lq + 0] = av.x; As[lr][lq + 1] = av.y;
        As[lr][lq + 2] = av.z; As[lr][lq + 3] = av.w;
        *(float4*)&Bs[bkk][bc] =
            *(const float4*)(B + (size_t)(k0 + bkk) * HH + cb + bc);
        __syncthreads();
        #pragma unroll
        for (int kk = 0; kk < 16; kk++) {
            float4 b = *(float4*)&Bs[kk][tx * 4];
            #pragma unroll
            for (int i = 0; i < 4; i++) {
                float a = As[ty * 4 + i][kk];
                acc[i].x += a * b.x; acc[i].y += a * b.y;
                acc[i].z += a * b.z; acc[i].w += a * b.w;
            }
        }
        __syncthreads();
    }
    #pragma unroll
    for (int i = 0; i < 4; i++) {
        int r = rb + ty * 4 + i;
        if (r < M) *(float4*)(C + (size_t)r * HH + cb + tx * 4) = acc[i];
    }
}

// ---------------- aggregation: out = relu(D^-1/2 A D^-1/2 h + b) -----------
// blockDim (64,4): 64 threads per node (4 cols each via float4), 4 nodes/block
__global__ __launch_bounds__(256, 4)
void k_agg(const float* __restrict__ h, const int* __restrict__ rowptr,
           const int* __restrict__ csr, const float* __restrict__ dinv,
           const float* __restrict__ bias, float* __restrict__ out) {
    int node = blockIdx.x * 4 + threadIdx.y;
    if (node >= NN) return;
    int c = threadIdx.x * 4;
    float di = dinv[node];

    float4 v = *(const float4*)(h + (size_t)node * HH + c);
    float w0 = di * di;
    float4 acc = make_float4(v.x * w0, v.y * w0, v.z * w0, v.w * w0);

    int lo = rowptr[node], hi = rowptr[node + 1];
    for (int e = lo; e < hi; e++) {
        int s = csr[e];
        float w = di * dinv[s];
        float4 u = *(const float4*)(h + (size_t)s * HH + c);
        acc.x += w * u.x; acc.y += w * u.y;
        acc.z += w * u.z; acc.w += w * u.w;
    }
    float4 b = *(const float4*)(bias + c);
    acc.x = fmaxf(acc.x + b.x, 0.f);
    acc.y = fmaxf(acc.y + b.y, 0.f);
    acc.z = fmaxf(acc.z + b.z, 0.f);
    acc.w = fmaxf(acc.w + b.w, 0.f);
    *(float4*)(out + (size_t)node * HH + c) = acc;
}

// ---------------- fused pair MLP: gather+concat -> fc1+relu -> fc2 -> sigmoid
// block = 256 threads (8 warps), 32 pairs/block (4 pairs/warp), K=512
__global__ __launch_bounds__(256, 2)
void k_fc(const float* __restrict__ embL, const float* __restrict__ embR,
          const int* __restrict__ y,
          const float* __restrict__ fcW, const float* __restrict__ fcb,
          const float* __restrict__ fc2W, const float* __restrict__ fc2b,
          float* __restrict__ out) {
    __shared__ float As[32][36];     // 36: 16B-aligned rows, no read conflicts
    __shared__ float Bs[32][256];
    __shared__ int sy0[32], sy1[32];

    int tid = threadIdx.x;
    int pbase = blockIdx.x * 32;
    if (tid < 32) {
        sy0[tid] = y[(pbase + tid) * 2 + 0];
        sy1[tid] = y[(pbase + tid) * 2 + 1];
    }
    __syncthreads();

    int w = tid >> 5, lane = tid & 31;
    float acc[4][8];
    #pragma unroll
    for (int p = 0; p < 4; p++)
        #pragma unroll
        for (int j = 0; j < 8; j++) acc[p][j] = 0.f;

    int ap = tid >> 3;          // A-gather pair 0..31
    int aq = (tid & 7) * 4;     // A-gather k offset within 32-tile

    for (int kt = 0; kt < 2 * HH; kt += 32) {
        // gather A: first 256 k from embL[y0], last 256 from embR[y1]
        {
            int kg = kt + aq;
            const float* base = (kg < HH)
                ? (embL + (size_t)sy0[ap] * HH + kg)
                : (embR + (size_t)sy1[ap] * HH + (kg - HH));
            *(float4*)&As[ap][aq] = *(const float4*)base;
        }
        // load B tile: fcW[kt..kt+32, 0..256)
        #pragma unroll
        for (int i = 0; i < 8; i++) {
            int idx = tid + i * 256;
            int kk = idx >> 6, cc = (idx & 63) * 4;
            *(float4*)&Bs[kk][cc] =
                *(const float4*)(fcW + (size_t)(kt + kk) * HH + cc);
        }
        __syncthreads();
        #pragma unroll
        for (int kk = 0; kk < 32; kk++) {
            float4 b0 = *(float4*)&Bs[kk][lane * 8];
            float4 b1 = *(float4*)&Bs[kk][lane * 8 + 4];
            #pragma unroll
            for (int pp = 0; pp < 4; pp++) {
                float a = As[w * 4 + pp][kk];
                acc[pp][0] += a * b0.x; acc[pp][1] += a * b0.y;
                acc[pp][2] += a * b0.z; acc[pp][3] += a * b0.w;
                acc[pp][4] += a * b1.x; acc[pp][5] += a * b1.y;
                acc[pp][6] += a * b1.z; acc[pp][7] += a * b1.w;
            }
        }
        __syncthreads();
    }

    // epilogue: relu + fc2 dot + sigmoid
    float fb[8], fw[8];
    #pragma unroll
    for (int j = 0; j < 8; j++) {
        fb[j] = fcb [lane * 8 + j];
        fw[j] = fc2W[lane * 8 + j];
    }
    float bias2 = fc2b[0];
    #pragma unroll
    for (int pp = 0; pp < 4; pp++) {
        float s = 0.f;
        #pragma unroll
        for (int j = 0; j < 8; j++) {
            float hv = acc[pp][j] + fb[j];
            hv = hv > 0.f ? hv : 0.f;
            s += hv * fw[j];
        }
        #pragma unroll
        for (int off = 16; off > 0; off >>= 1)
            s += __shfl_xor_sync(0xffffffffu, s, off);
        if (lane == 0) {
            int pi = pbase + w * 4 + pp;
            out[pi] = 1.f / (1.f + expf(-(s + bias2)));
        }
    }
}

// ---------------- launch ---------------------------------------------------
extern "C" void kernel_launch(void* const* d_in, const int* in_sizes, int n_in,
                              void* d_out, int out_size) {
    const float* x_s  = (const float*)d_in[0];
    const float* x_t  = (const float*)d_in[1];
    const int*   ei_s = (const int*)  d_in[2];
    const int*   ei_t = (const int*)  d_in[3];
    const int*   y    = (const int*)  d_in[4];
    const float* W1   = (const float*)d_in[5];
    const float* b1   = (const float*)d_in[6];
    const float* W2   = (const float*)d_in[7];
    const float* b2   = (const float*)d_in[8];
    const float* fcW  = (const float*)d_in[9];
    const float* fcb  = (const float*)d_in[10];
    const float* fc2W = (const float*)d_in[11];
    const float* fc2b = (const float*)d_in[12];
    float* out = (float*)d_out;

    float *h, *embL, *embR, *dinvp;
    int *degp, *rowp, *wp, *csrp;
    cudaGetSymbolAddress((void**)&h,     g_h);
    cudaGetSymbolAddress((void**)&embL,  g_embL);
    cudaGetSymbolAddress((void**)&embR,  g_embR);
    cudaGetSymbolAddress((void**)&degp,  g_deg);
    cudaGetSymbolAddress((void**)&dinvp, g_dinv);
    cudaGetSymbolAddress((void**)&rowp,  g_rowptr);
    cudaGetSymbolAddress((void**)&wp,    g_wptr);
    cudaGetSymbolAddress((void**)&csrp,  g_csr);

    const int* ei[2]  = { ei_s, ei_t };
    int nb_n = (NN + 255) / 256;
    int nb_e = (EE + 255) / 256;

    for (int side = 0; side < 2; side++) {
        int*   deg = degp  + side * NN;
        float* dv  = dinvp + side * NN;
        int*   rp  = rowp  + side * (NN + 1);
        int*   wpt = wp    + side * NN;
        int*   cs  = csrp  + side * EE;
        k_init_deg<<<nb_n, 256>>>(deg);
        k_count  <<<nb_e, 256>>>(ei[side], deg);
        k_dinv   <<<nb_n, 256>>>(deg, dv);
        k_scan   <<<1, 1024>>>(deg, rp, wpt);
        k_fill   <<<nb_e, 256>>>(ei[side], wpt, cs);
    }

    dim3 ggrid((NN + 63) / 64, HH / 64);
    int agrid = (NN + 3) / 4;
    dim3 ablk(64, 4);

    // left side (x_s, graph s)
    k_gemm<<<ggrid, 256>>>(x_s, W1, h, NN, DIN);
    k_agg <<<agrid, ablk>>>(h, rowp, csrp, dinvp, b1, embL);
    k_gemm<<<ggrid, 256>>>(embL, W2, h, NN, HH);
    k_agg <<<agrid, ablk>>>(h, rowp, csrp, dinvp, b2, embL);

    // right side (x_t, graph t)
    k_gemm<<<ggrid, 256>>>(x_t, W1, h, NN, DIN);
    k_agg <<<agrid, ablk>>>(h, rowp + (NN + 1), csrp + EE, dinvp + NN, b1, embR);
    k_gemm<<<ggrid, 256>>>(embR, W2, h, NN, HH);
    k_agg <<<agrid, ablk>>>(h, rowp + (NN + 1), csrp + EE, dinvp + NN, b2, embR);

    // fused pair MLP
    k_fc<<<PP / 32, 256>>>(embL, embR, y, fcW, fcb, fc2W, fc2b, out);
}

// round 3
// speedup vs baseline: 1.3325x; 1.3283x over previous
#include <cuda_runtime.h>
#include <math.h>

#define NN 50000
#define EE 500000
#define DIN 128
#define HH 256
#define PP 100000
#define NSB 128
#define CHUNK ((NN + NSB - 1) / NSB)
#define AST 136

__device__ float g_h [NN*HH];
__device__ float g_Ah[NN*HH];
__device__ float g_Al[NN*HH];
__device__ float g_ZL[NN*HH];
__device__ float g_ZR[NN*HH];
__device__ float g_Bh[229376];
__device__ float g_Bl[229376];
__device__ int   g_deg[2*NN];
__device__ float g_dinv[2*NN];
__device__ int   g_rowptr[2*(NN+1)];
__device__ int   g_wptr[2*NN];
__device__ int   g_csr[2*EE];
__device__ int   g_bsum[2*NSB];
__device__ int   g_boff[2*NSB];

__device__ __forceinline__ void split2(float x, float& hi, float& lo) {
    unsigned u;
    asm("cvt.rna.tf32.f32 %0, %1;" : "=r"(u) : "f"(x));
    hi = __uint_as_float(u);
    float r = x - hi;
    asm("cvt.rna.tf32.f32 %0, %1;" : "=r"(u) : "f"(r));
    lo = __uint_as_float(u);
}

__device__ __forceinline__ void mma_tf32(float* d, unsigned a0, unsigned a1,
                                         unsigned a2, unsigned a3,
                                         unsigned b0, unsigned b1) {
    asm volatile(
        "mma.sync.aligned.m16n8k8.row.col.f32.tf32.tf32.f32 "
        "{%0,%1,%2,%3}, {%4,%5,%6,%7}, {%8,%9}, {%0,%1,%2,%3};"
        : "+f"(d[0]), "+f"(d[1]), "+f"(d[2]), "+f"(d[3])
        : "r"(a0), "r"(a1), "r"(a2), "r"(a3), "r"(b0), "r"(b1));
}

// ---------------- CSR build (gridDim.y = side) ------------------------------
__global__ void k_init_deg(int* deg) {
    int i = blockIdx.x * blockDim.x + threadIdx.x;
    if (i < NN) deg[blockIdx.y * NN + i] = 1;
}
__global__ void k_count(const int* __restrict__ es, const int* __restrict__ et,
                        int* __restrict__ deg) {
    int e = blockIdx.x * blockDim.x + threadIdx.x;
    const int* ei = blockIdx.y ? et : es;
    if (e < EE) atomicAdd(&deg[blockIdx.y * NN + ei[EE + e]], 1);
}
__global__ void k_dinv(const int* __restrict__ deg, float* __restrict__ dinv) {
    int i = blockIdx.x * blockDim.x + threadIdx.x;
    if (i < NN) dinv[blockIdx.y * NN + i] = rsqrtf((float)deg[blockIdx.y * NN + i]);
}
__global__ void k_scan1(const int* __restrict__ deg, int* __restrict__ bsum) {
    const int* d = deg + blockIdx.y * NN;
    int lo = blockIdx.x * CHUNK, hi = min(lo + CHUNK, NN);
    int s = 0;
    for (int i = lo + threadIdx.x; i < hi; i += 256) s += d[i] - 1;
    __shared__ int sh[8];
    int lane = threadIdx.x & 31, w = threadIdx.x >> 5;
    #pragma unroll
    for (int o = 16; o > 0; o >>= 1) s += __shfl_down_sync(~0u, s, o);
    if (lane == 0) sh[w] = s;
    __syncthreads();
    if (threadIdx.x == 0) {
        int t = 0;
        #pragma unroll
        for (int j = 0; j < 8; j++) t += sh[j];
        bsum[blockIdx.y * NSB + blockIdx.x] = t;
    }
}
__global__ void k_scan2(const int* __restrict__ bsum, int* __restrict__ boff,
                        int* __restrict__ rowptr) {
    __shared__ int sb[NSB];
    int t = threadIdx.x, side = blockIdx.y;
    int orig = bsum[side * NSB + t];
    sb[t] = orig;
    __syncthreads();
    for (int o = 1; o < NSB; o <<= 1) {
        int v = (t >= o) ? sb[t - o] : 0;
        __syncthreads();
        sb[t] += v;
        __syncthreads();
    }
    boff[side * NSB + t] = sb[t] - orig;
    if (t == 0) rowptr[side * (NN + 1) + NN] = EE;
}
__global__ void k_scan3(const int* __restrict__ deg, const int* __restrict__ boff,
                        int* __restrict__ rowptr, int* __restrict__ wptr) {
    int side = blockIdx.y;
    const int* d = deg + side * NN;
    int* rp = rowptr + side * (NN + 1);
    int* wp = wptr + side * NN;
    int lo = blockIdx.x * CHUNK, hi = min(lo + CHUNK, NN);
    __shared__ int wsum[8];
    __shared__ int srun;
    if (threadIdx.x == 0) srun = boff[side * NSB + blockIdx.x];
    __syncthreads();
    int lane = threadIdx.x & 31, w = threadIdx.x >> 5;
    for (int t0 = lo; t0 < hi; t0 += 256) {
        int i = t0 + threadIdx.x;
        int v = (i < hi) ? d[i] - 1 : 0;
        int incl = v;
        #pragma unroll
        for (int o = 1; o < 32; o <<= 1) {
            int u = __shfl_up_sync(~0u, incl, o);
            if (lane >= o) incl += u;
        }
        if (lane == 31) wsum[w] = incl;
        __syncthreads();
        int woff = 0;
        for (int j = 0; j < w; j++) woff += wsum[j];
        if (i < hi) { int e = srun + woff + incl - v; rp[i] = e; wp[i] = e; }
        __syncthreads();
        if (threadIdx.x == 255) srun += woff + incl;
        __syncthreads();
    }
}
__global__ void k_fill(const int* __restrict__ es, const int* __restrict__ et,
                       int* __restrict__ wptr, int* __restrict__ csr) {
    int e = blockIdx.x * blockDim.x + threadIdx.x;
    const int* ei = blockIdx.y ? et : es;
    if (e < EE) {
        int p = atomicAdd(&wptr[blockIdx.y * NN + ei[EE + e]], 1);
        csr[blockIdx.y * EE + p] = ei[e];
    }
}

// ---------------- tf32 hi/lo splitter ---------------------------------------
__global__ void k_split(const float* __restrict__ s, float* __restrict__ dh,
                        float* __restrict__ dl, int n4) {
    int i = blockIdx.x * blockDim.x + threadIdx.x;
    if (i >= n4) return;
    float4 v = ((const float4*)s)[i];
    float4 h, l;
    split2(v.x, h.x, l.x); split2(v.y, h.y, l.y);
    split2(v.z, h.z, l.z); split2(v.w, h.w, l.w);
    ((float4*)dh)[i] = h;
    ((float4*)dl)[i] = l;
}

// ---------------- 3xTF32 tensor-core GEMM: C[M,256]=A[M,K]@B[K,256] ---------
__global__ __launch_bounds__(256)
void k_gemm_tc(const float* __restrict__ Ah, const float* __restrict__ Al,
               const float* __restrict__ Bh, const float* __restrict__ Bl,
               float* __restrict__ C, int M, int K) {
    __shared__ float Ash[16*AST], Asl[16*AST], Bsh[16*AST], Bsl[16*AST];
    int tid = threadIdx.x, lane = tid & 31, wid = tid >> 5;
    int wm = wid & 1, wn = wid >> 1;
    int g = lane >> 2, tg = lane & 3;
    int rb = blockIdx.x * 128, cb = blockIdx.y * 128;

    float acc[4][4][4];
    #pragma unroll
    for (int a = 0; a < 4; a++)
        #pragma unroll
        for (int b = 0; b < 4; b++)
            #pragma unroll
            for (int c = 0; c < 4; c++) acc[a][b][c] = 0.f;

    int srow = tid & 127, skh = (tid >> 7) * 8;
    int bk = tid >> 4, bn = (tid & 15) * 4;

    for (int k0 = 0; k0 < K; k0 += 16) {
        // stage A transposed to [k][row]
        float4 h0, h1, l0, l1;
        int ar = rb + srow;
        if (ar < M) {
            const float* pa = Ah + (size_t)ar * K + k0 + skh;
            const float* pl = Al + (size_t)ar * K + k0 + skh;
            h0 = *(const float4*)pa; h1 = *(const float4*)(pa + 4);
            l0 = *(const float4*)pl; l1 = *(const float4*)(pl + 4);
        } else { h0 = h1 = l0 = l1 = make_float4(0.f,0.f,0.f,0.f); }
        Ash[(skh+0)*AST+srow]=h0.x; Ash[(skh+1)*AST+srow]=h0.y;
        Ash[(skh+2)*AST+srow]=h0.z; Ash[(skh+3)*AST+srow]=h0.w;
        Ash[(skh+4)*AST+srow]=h1.x; Ash[(skh+5)*AST+srow]=h1.y;
        Ash[(skh+6)*AST+srow]=h1.z; Ash[(skh+7)*AST+srow]=h1.w;
        Asl[(skh+0)*AST+srow]=l0.x; Asl[(skh+1)*AST+srow]=l0.y;
        Asl[(skh+2)*AST+srow]=l0.z; Asl[(skh+3)*AST+srow]=l0.w;
        Asl[(skh+4)*AST+srow]=l1.x; Asl[(skh+5)*AST+srow]=l1.y;
        Asl[(skh+6)*AST+srow]=l1.z; Asl[(skh+7)*AST+srow]=l1.w;
        // stage B [k][n]
        {
            const float* pb = Bh + (size_t)(k0 + bk) * HH + cb + bn;
            const float* pl = Bl + (size_t)(k0 + bk) * HH + cb + bn;
            *(float4*)&Bsh[bk*AST+bn]    = *(const float4*)pb;
            *(float4*)&Bsh[bk*AST+bn+64] = *(const float4*)(pb + 64);
            *(float4*)&Bsl[bk*AST+bn]    = *(const float4*)pl;
            *(float4*)&Bsl[bk*AST+bn+64] = *(const float4*)(pl + 64);
        }
        __syncthreads();
        #pragma unroll
        for (int ks = 0; ks < 2; ks++) {
            int kb = ks * 8;
            unsigned b0h[4], b1h[4], b0l[4], b1l[4];
            #pragma unroll
            for (int nt = 0; nt < 4; nt++) {
                int n = wn * 32 + nt * 8 + g;
                b0h[nt] = __float_as_uint(Bsh[(kb+tg)*AST+n]);
                b1h[nt] = __float_as_uint(Bsh[(kb+tg+4)*AST+n]);
                b0l[nt] = __float_as_uint(Bsl[(kb+tg)*AST+n]);
                b1l[nt] = __float_as_uint(Bsl[(kb+tg+4)*AST+n]);
            }
            #pragma unroll
            for (int mt = 0; mt < 4; mt++) {
                int r = wm * 64 + mt * 16 + g;
                unsigned ah0 = __float_as_uint(Ash[(kb+tg)*AST+r]);
                unsigned ah1 = __float_as_uint(Ash[(kb+tg)*AST+r+8]);
                unsigned ah2 = __float_as_uint(Ash[(kb+tg+4)*AST+r]);
                unsigned ah3 = __float_as_uint(Ash[(kb+tg+4)*AST+r+8]);
                unsigned al0 = __float_as_uint(Asl[(kb+tg)*AST+r]);
                unsigned al1 = __float_as_uint(Asl[(kb+tg)*AST+r+8]);
                unsigned al2 = __float_as_uint(Asl[(kb+tg+4)*AST+r]);
                unsigned al3 = __float_as_uint(Asl[(kb+tg+4)*AST+r+8]);
                #pragma unroll
                for (int nt = 0; nt < 4; nt++) {
                    mma_tf32(acc[mt][nt], ah0, ah1, ah2, ah3, b0h[nt], b1h[nt]);
                    mma_tf32(acc[mt][nt], ah0, ah1, ah2, ah3, b0l[nt], b1l[nt]);
                    mma_tf32(acc[mt][nt], al0, al1, al2, al3, b0h[nt], b1h[nt]);
                }
            }
        }
        __syncthreads();
    }
    #pragma unroll
    for (int mt = 0; mt < 4; mt++) {
        int r0 = rb + wm * 64 + mt * 16 + g;
        #pragma unroll
        for (int nt = 0; nt < 4; nt++) {
            int c = cb + wn * 32 + nt * 8 + tg * 2;
            if (r0 < M)
                *(float2*)(C + (size_t)r0 * HH + c) = make_float2(acc[mt][nt][0], acc[mt][nt][1]);
            if (r0 + 8 < M)
                *(float2*)(C + (size_t)(r0+8) * HH + c) = make_float2(acc[mt][nt][2], acc[mt][nt][3]);
        }
    }
}

// ---------------- aggregation + relu, emits tf32 hi/lo splits ---------------
__global__ __launch_bounds__(256, 4)
void k_agg(const float* __restrict__ h, const int* __restrict__ rowptr,
           const int* __restrict__ csr, const float* __restrict__ dinv,
           const float* __restrict__ bias, float* __restrict__ oh,
           float* __restrict__ ol) {
    int node = blockIdx.x * 4 + threadIdx.y;
    if (node >= NN) return;
    int c = threadIdx.x * 4;
    float di = dinv[node];
    float4 v = *(const float4*)(h + (size_t)node * HH + c);
    float w0 = di * di;
    float4 acc = make_float4(v.x*w0, v.y*w0, v.z*w0, v.w*w0);
    int lo = rowptr[node], hi = rowptr[node + 1];
    for (int e = lo; e < hi; e++) {
        int s = csr[e];
        float w = di * dinv[s];
        float4 u = *(const float4*)(h + (size_t)s * HH + c);
        acc.x += w*u.x; acc.y += w*u.y; acc.z += w*u.z; acc.w += w*u.w;
    }
    float4 b = *(const float4*)(bias + c);
    acc.x = fmaxf(acc.x + b.x, 0.f); acc.y = fmaxf(acc.y + b.y, 0.f);
    acc.z = fmaxf(acc.z + b.z, 0.f); acc.w = fmaxf(acc.w + b.w, 0.f);
    float4 hh, ll;
    split2(acc.x, hh.x, ll.x); split2(acc.y, hh.y, ll.y);
    split2(acc.z, hh.z, ll.z); split2(acc.w, hh.w, ll.w);
    *(float4*)(oh + (size_t)node * HH + c) = hh;
    *(float4*)(ol + (size_t)node * HH + c) = ll;
}

// ---------------- pair epilogue: sigmoid(relu(ZL[y0]+ZR[y1]+b1)@W2 + b2) ----
__global__ __launch_bounds__(256)
void k_pair(const float* __restrict__ ZL, const float* __restrict__ ZR,
            const int* __restrict__ y, const float* __restrict__ fcb,
            const float* __restrict__ fc2W, const float* __restrict__ fc2b,
            float* __restrict__ out) {
    int w = threadIdx.x >> 5, lane = threadIdx.x & 31;
    int p = blockIdx.x * 8 + w;
    if (p >= PP) return;
    int y0 = y[2*p], y1 = y[2*p+1];
    int c = lane * 8;
    float s = 0.f;
    #pragma unroll
    for (int q = 0; q < 2; q++) {
        int cc = c + q * 4;
        float4 a = *(const float4*)(ZL + (size_t)y0 * HH + cc);
        float4 b = *(const float4*)(ZR + (size_t)y1 * HH + cc);
        float4 fb = *(const float4*)(fcb + cc);
        float4 fw = *(const float4*)(fc2W + cc);
        s += fmaxf(a.x + b.x + fb.x, 0.f) * fw.x;
        s += fmaxf(a.y + b.y + fb.y, 0.f) * fw.y;
        s += fmaxf(a.z + b.z + fb.z, 0.f) * fw.z;
        s += fmaxf(a.w + b.w + fb.w, 0.f) * fw.w;
    }
    #pragma unroll
    for (int o = 16; o > 0; o >>= 1) s += __shfl_xor_sync(~0u, s, o);
    if (lane == 0) out[p] = 1.f / (1.f + expf(-(s + fc2b[0])));
}

// ---------------- launch ----------------------------------------------------
extern "C" void kernel_launch(void* const* d_in, const int* in_sizes, int n_in,
                              void* d_out, int out_size) {
    const float* x_s  = (const float*)d_in[0];
    const float* x_t  = (const float*)d_in[1];
    const int*   ei_s = (const int*)  d_in[2];
    const int*   ei_t = (const int*)  d_in[3];
    const int*   y    = (const int*)  d_in[4];
    const float* W1   = (const float*)d_in[5];
    const float* b1   = (const float*)d_in[6];
    const float* W2   = (const float*)d_in[7];
    const float* b2   = (const float*)d_in[8];
    const float* fcW  = (const float*)d_in[9];
    const float* fcb  = (const float*)d_in[10];
    const float* fc2W = (const float*)d_in[11];
    const float* fc2b = (const float*)d_in[12];
    float* out = (float*)d_out;

    float *h, *Ah, *Al, *ZL, *ZR, *Bh, *Bl, *dv;
    int *deg, *rp, *wp, *cs, *bs, *bo;
    cudaGetSymbolAddress((void**)&h,  g_h);
    cudaGetSymbolAddress((void**)&Ah, g_Ah);
    cudaGetSymbolAddress((void**)&Al, g_Al);
    cudaGetSymbolAddress((void**)&ZL, g_ZL);
    cudaGetSymbolAddress((void**)&ZR, g_ZR);
    cudaGetSymbolAddress((void**)&Bh, g_Bh);
    cudaGetSymbolAddress((void**)&Bl, g_Bl);
    cudaGetSymbolAddress((void**)&dv, g_dinv);
    cudaGetSymbolAddress((void**)&deg, g_deg);
    cudaGetSymbolAddress((void**)&rp, g_rowptr);
    cudaGetSymbolAddress((void**)&wp, g_wptr);
    cudaGetSymbolAddress((void**)&cs, g_csr);
    cudaGetSymbolAddress((void**)&bs, g_bsum);
    cudaGetSymbolAddress((void**)&bo, g_boff);

    dim3 gn((NN + 255) / 256, 2), ge((EE + 255) / 256, 2);
    k_init_deg<<<gn, 256>>>(deg);
    k_count<<<ge, 256>>>(ei_s, ei_t, deg);
    k_dinv<<<gn, 256>>>(deg, dv);
    k_scan1<<<dim3(NSB, 2), 256>>>(deg, bs);
    k_scan2<<<dim3(1, 2), NSB>>>(bs, bo, rp);
    k_scan3<<<dim3(NSB, 2), 256>>>(deg, bo, rp, wp);
    k_fill<<<ge, 256>>>(ei_s, ei_t, wp, cs);

    k_split<<<32, 256>>>(W1, Bh, Bl, 8192);
    k_split<<<64, 256>>>(W2, Bh + 32768, Bl + 32768, 16384);
    k_split<<<128, 256>>>(fcW, Bh + 98304, Bl + 98304, 32768);

    dim3 gg((NN + 127) / 128, 2);
    int ag = (NN + 3) / 4;
    dim3 ab(64, 4);

    k_split<<<6250, 256>>>(x_s, Ah, Al, NN * DIN / 4);
    k_gemm_tc<<<gg, 256>>>(Ah, Al, Bh, Bl, h, NN, DIN);
    k_agg<<<ag, ab>>>(h, rp, cs, dv, b1, Ah, Al);
    k_gemm_tc<<<gg, 256>>>(Ah, Al, Bh + 32768, Bl + 32768, h, NN, HH);
    k_agg<<<ag, ab>>>(h, rp, cs, dv, b2, Ah, Al);
    k_gemm_tc<<<gg, 256>>>(Ah, Al, Bh + 98304, Bl + 98304, ZL, NN, HH);

    k_split<<<6250, 256>>>(x_t, Ah, Al, NN * DIN / 4);
    k_gemm_tc<<<gg, 256>>>(Ah, Al, Bh, Bl, h, NN, DIN);
    k_agg<<<ag, ab>>>(h, rp + NN + 1, cs + EE, dv + NN, b1, Ah, Al);
    k_gemm_tc<<<gg, 256>>>(Ah, Al, Bh + 32768, Bl + 32768, h, NN, HH);
    k_agg<<<ag, ab>>>(h, rp + NN + 1, cs + EE, dv + NN, b2, Ah, Al);
    k_gemm_tc<<<gg, 256>>>(Ah, Al, Bh + 163840, Bl + 163840, ZR, NN, HH);

    k_pair<<<(PP + 7) / 8, 256>>>(ZL, ZR, y, fcb, fc2W, fc2b, out);
}

// round 4
// speedup vs baseline: 2.7159x; 2.0383x over previous
#include <cuda_runtime.h>
#include <cuda_bf16.h>
#include <math.h>

#define NN 50000
#define EE 500000
#define DIN 128
#define HH 256
#define PP 100000
#define NSB 128
#define CHUNK ((NN + NSB - 1) / NSB)
#define BST 40   // bf16 row stride (80B) -> conflict-free ldmatrix

__device__ float g_h [NN*HH];
__device__ __nv_bfloat16 g_Ah[NN*HH];
__device__ __nv_bfloat16 g_Al[NN*HH];
__device__ float g_ZL[NN*HH];
__device__ float g_ZR[NN*HH];
__device__ __nv_bfloat16 g_Bh[229376];
__device__ __nv_bfloat16 g_Bl[229376];
__device__ int   g_deg[2*NN];
__device__ float g_dinv[2*NN];
__device__ int   g_rowptr[2*(NN+1)];
__device__ int   g_wptr[2*NN];
__device__ int   g_csr[2*EE];
__device__ int   g_bsum[2*NSB];
__device__ int   g_boff[2*NSB];

__device__ __forceinline__ void bsplit(float x, __nv_bfloat16& h, __nv_bfloat16& l) {
    h = __float2bfloat16_rn(x);
    l = __float2bfloat16_rn(x - __bfloat162float(h));
}

#define LDM4(R, A) asm volatile( \
    "ldmatrix.sync.aligned.m8n8.x4.shared.b16 {%0,%1,%2,%3}, [%4];" \
    : "=r"(R[0]),"=r"(R[1]),"=r"(R[2]),"=r"(R[3]) : "r"(A))
#define MMAB(D, A, B0, B1) asm volatile( \
    "mma.sync.aligned.m16n8k16.row.col.f32.bf16.bf16.f32 " \
    "{%0,%1,%2,%3},{%4,%5,%6,%7},{%8,%9},{%0,%1,%2,%3};" \
    : "+f"(D[0]),"+f"(D[1]),"+f"(D[2]),"+f"(D[3]) \
    : "r"(A[0]),"r"(A[1]),"r"(A[2]),"r"(A[3]),"r"(B0),"r"(B1))
#define CPA(D, S, SZ) asm volatile( \
    "cp.async.cg.shared.global [%0],[%1],16,%2;" :: "r"(D),"l"(S),"r"(SZ))

// ---------------- CSR build (gridDim.y = side) ------------------------------
__global__ void k_init_deg(int* deg) {
    int i = blockIdx.x * blockDim.x + threadIdx.x;
    if (i < NN) deg[blockIdx.y * NN + i] = 1;
}
__global__ void k_count(const int* __restrict__ es, const int* __restrict__ et,
                        int* __restrict__ deg) {
    int e = blockIdx.x * blockDim.x + threadIdx.x;
    const int* ei = blockIdx.y ? et : es;
    if (e < EE) atomicAdd(&deg[blockIdx.y * NN + ei[EE + e]], 1);
}
__global__ void k_dinv(const int* __restrict__ deg, float* __restrict__ dinv) {
    int i = blockIdx.x * blockDim.x + threadIdx.x;
    if (i < NN) dinv[blockIdx.y * NN + i] = rsqrtf((float)deg[blockIdx.y * NN + i]);
}
__global__ void k_scan1(const int* __restrict__ deg, int* __restrict__ bsum) {
    const int* d = deg + blockIdx.y * NN;
    int lo = blockIdx.x * CHUNK, hi = min(lo + CHUNK, NN);
    int s = 0;
    for (int i = lo + threadIdx.x; i < hi; i += 256) s += d[i] - 1;
    __shared__ int sh[8];
    int lane = threadIdx.x & 31, w = threadIdx.x >> 5;
    #pragma unroll
    for (int o = 16; o > 0; o >>= 1) s += __shfl_down_sync(~0u, s, o);
    if (lane == 0) sh[w] = s;
    __syncthreads();
    if (threadIdx.x == 0) {
        int t = 0;
        #pragma unroll
        for (int j = 0; j < 8; j++) t += sh[j];
        bsum[blockIdx.y * NSB + blockIdx.x] = t;
    }
}
__global__ void k_scan2(const int* __restrict__ bsum, int* __restrict__ boff,
                        int* __restrict__ rowptr) {
    __shared__ int sb[NSB];
    int t = threadIdx.x, side = blockIdx.y;
    int orig = bsum[side * NSB + t];
    sb[t] = orig;
    __syncthreads();
    for (int o = 1; o < NSB; o <<= 1) {
        int v = (t >= o) ? sb[t - o] : 0;
        __syncthreads();
        sb[t] += v;
        __syncthreads();
    }
    boff[side * NSB + t] = sb[t] - orig;
    if (t == 0) rowptr[side * (NN + 1) + NN] = EE;
}
__global__ void k_scan3(const int* __restrict__ deg, const int* __restrict__ boff,
                        int* __restrict__ rowptr, int* __restrict__ wptr) {
    int side = blockIdx.y;
    const int* d = deg + side * NN;
    int* rp = rowptr + side * (NN + 1);
    int* wp = wptr + side * NN;
    int lo = blockIdx.x * CHUNK, hi = min(lo + CHUNK, NN);
    __shared__ int wsum[8];
    __shared__ int srun;
    if (threadIdx.x == 0) srun = boff[side * NSB + blockIdx.x];
    __syncthreads();
    int lane = threadIdx.x & 31, w = threadIdx.x >> 5;
    for (int t0 = lo; t0 < hi; t0 += 256) {
        int i = t0 + threadIdx.x;
        int v = (i < hi) ? d[i] - 1 : 0;
        int incl = v;
        #pragma unroll
        for (int o = 1; o < 32; o <<= 1) {
            int u = __shfl_up_sync(~0u, incl, o);
            if (lane >= o) incl += u;
        }
        if (lane == 31) wsum[w] = incl;
        __syncthreads();
        int woff = 0;
        for (int j = 0; j < w; j++) woff += wsum[j];
        if (i < hi) { int e = srun + woff + incl - v; rp[i] = e; wp[i] = e; }
        __syncthreads();
        if (threadIdx.x == 255) srun += woff + incl;
        __syncthreads();
    }
}
__global__ void k_fill(const int* __restrict__ es, const int* __restrict__ et,
                       int* __restrict__ wptr, int* __restrict__ csr) {
    int e = blockIdx.x * blockDim.x + threadIdx.x;
    const int* ei = blockIdx.y ? et : es;
    if (e < EE) {
        int p = atomicAdd(&wptr[blockIdx.y * NN + ei[EE + e]], 1);
        csr[blockIdx.y * EE + p] = ei[e];
    }
}

// ---------------- splitters -------------------------------------------------
__global__ void k_split_x(const float* __restrict__ s, __nv_bfloat16* __restrict__ dh,
                          __nv_bfloat16* __restrict__ dl, int n4) {
    int i = blockIdx.x * blockDim.x + threadIdx.x;
    if (i >= n4) return;
    float4 v = ((const float4*)s)[i];
    union { __nv_bfloat16 b[4]; uint2 u; } H, L;
    bsplit(v.x, H.b[0], L.b[0]); bsplit(v.y, H.b[1], L.b[1]);
    bsplit(v.z, H.b[2], L.b[2]); bsplit(v.w, H.b[3], L.b[3]);
    ((uint2*)dh)[i] = H.u;
    ((uint2*)dl)[i] = L.u;
}

// transpose W[K,N] (row stride N) -> Bt[n*K + k], split bf16 hi/lo
__global__ void k_wsplit(const float* __restrict__ W, __nv_bfloat16* __restrict__ th,
                         __nv_bfloat16* __restrict__ tl, int K, int N) {
    __shared__ float sh[32][33];
    int k0 = blockIdx.x * 32, n0 = blockIdx.y * 32;
    int tx = threadIdx.x, ty = threadIdx.y;
    #pragma unroll
    for (int j = 0; j < 4; j++)
        sh[ty + j * 8][tx] = W[(size_t)(k0 + ty + j * 8) * N + n0 + tx];
    __syncthreads();
    #pragma unroll
    for (int j = 0; j < 4; j++) {
        int nn = ty + j * 8;
        float v = sh[tx][nn];
        __nv_bfloat16 h, l;
        bsplit(v, h, l);
        th[(size_t)(n0 + nn) * K + k0 + tx] = h;
        tl[(size_t)(n0 + nn) * K + k0 + tx] = l;
    }
}

// ---------------- bf16x3 tensor-core GEMM: C[M,256]=A[M,K]@B[K,256] ---------
// A bf16 [M,K] row-major (hi/lo), B bf16 [256,K] n-major (hi/lo), C fp32.
__global__ __launch_bounds__(256)
void k_gemm_bf(const __nv_bfloat16* __restrict__ Ah, const __nv_bfloat16* __restrict__ Al,
               const __nv_bfloat16* __restrict__ Bth, const __nv_bfloat16* __restrict__ Btl,
               float* __restrict__ C, int M, int K) {
    extern __shared__ __nv_bfloat16 smem_dyn[];
    unsigned smb = (unsigned)__cvta_generic_to_shared(smem_dyn);
    int tid = threadIdx.x, lane = tid & 31, wid = tid >> 5;
    int wm = wid & 1, wn = wid >> 1;
    int rb = blockIdx.x * 128, cb = blockIdx.y * 128;
    int T = K >> 5;

    float acc[4][4][4];
    #pragma unroll
    for (int a = 0; a < 4; a++)
        #pragma unroll
        for (int b = 0; b < 4; b++)
            #pragma unroll
            for (int c = 0; c < 4; c++) acc[a][b][c] = 0.f;

    int srow = tid >> 1, half = tid & 1;
    int gA = rb + srow;
    int szA = (gA < M) ? 16 : 0;
    if (gA >= M) gA = M - 1;
    const __nv_bfloat16* pa = Ah  + (size_t)gA * K + half * 16;
    const __nv_bfloat16* pl = Al  + (size_t)gA * K + half * 16;
    const __nv_bfloat16* pb = Bth + (size_t)(cb + srow) * K + half * 16;
    const __nv_bfloat16* pq = Btl + (size_t)(cb + srow) * K + half * 16;
    unsigned sd = (unsigned)((srow * BST + half * 16) * 2);

    auto stage = [&](int t, int buf) {
        unsigned o = smb + buf * 10240 + sd;
        const __nv_bfloat16* a0 = pa + t * 32;
        CPA(o,      a0,     szA); CPA(o + 16,     a0 + 8, szA);
        const __nv_bfloat16* a1 = pl + t * 32;
        CPA(o + 20480, a1, szA);  CPA(o + 20496, a1 + 8, szA);
        const __nv_bfloat16* b0 = pb + t * 32;
        CPA(o + 40960, b0, 16);   CPA(o + 40976, b0 + 8, 16);
        const __nv_bfloat16* b1 = pq + t * 32;
        CPA(o + 61440, b1, 16);   CPA(o + 61456, b1 + 8, 16);
    };

    stage(0, 0);
    asm volatile("cp.async.commit_group;");

    for (int t = 0; t < T; t++) {
        int buf = t & 1;
        if (t + 1 < T) {
            stage(t + 1, buf ^ 1);
            asm volatile("cp.async.commit_group;");
            asm volatile("cp.async.wait_group 1;");
        } else {
            asm volatile("cp.async.wait_group 0;");
        }
        __syncthreads();

        unsigned pAh = smb + buf * 10240;
        unsigned pAl = pAh + 20480;
        unsigned pBh = pAh + 40960;
        unsigned pBl = pAh + 61440;

        #pragma unroll
        for (int ks = 0; ks < 2; ks++) {
            unsigned ah[4][4], al[4][4], bh[2][4], bl[2][4];
            int ach = ks * 2 + (lane >> 4);
            int arow = wm * 64 + (lane & 15);
            #pragma unroll
            for (int mt = 0; mt < 4; mt++) {
                unsigned off = (unsigned)(((arow + mt * 16) * BST + ach * 8) * 2);
                LDM4(ah[mt], pAh + off);
                LDM4(al[mt], pAl + off);
            }
            int bch = ks * 2 + ((lane >> 3) & 1);
            int brow = wn * 32 + (lane & 7) + (lane >> 4) * 8;
            #pragma unroll
            for (int p = 0; p < 2; p++) {
                unsigned off = (unsigned)(((brow + p * 16) * BST + bch * 8) * 2);
                LDM4(bh[p], pBh + off);
                LDM4(bl[p], pBl + off);
            }
            #pragma unroll
            for (int mt = 0; mt < 4; mt++)
                #pragma unroll
                for (int nt = 0; nt < 4; nt++)
                    MMAB(acc[mt][nt], ah[mt], bh[nt >> 1][(nt & 1) * 2], bh[nt >> 1][(nt & 1) * 2 + 1]);
            #pragma unroll
            for (int mt = 0; mt < 4; mt++)
                #pragma unroll
                for (int nt = 0; nt < 4; nt++)
                    MMAB(acc[mt][nt], ah[mt], bl[nt >> 1][(nt & 1) * 2], bl[nt >> 1][(nt & 1) * 2 + 1]);
            #pragma unroll
            for (int mt = 0; mt < 4; mt++)
                #pragma unroll
                for (int nt = 0; nt < 4; nt++)
                    MMAB(acc[mt][nt], al[mt], bh[nt >> 1][(nt & 1) * 2], bh[nt >> 1][(nt & 1) * 2 + 1]);
        }
        __syncthreads();
    }

    int g = lane >> 2, tg = lane & 3;
    #pragma unroll
    for (int mt = 0; mt < 4; mt++) {
        int r0 = rb + wm * 64 + mt * 16 + g;
        #pragma unroll
        for (int nt = 0; nt < 4; nt++) {
            int c = cb + wn * 32 + nt * 8 + tg * 2;
            if (r0 < M)
                *(float2*)(C + (size_t)r0 * HH + c) = make_float2(acc[mt][nt][0], acc[mt][nt][1]);
            if (r0 + 8 < M)
                *(float2*)(C + (size_t)(r0 + 8) * HH + c) = make_float2(acc[mt][nt][2], acc[mt][nt][3]);
        }
    }
}

// ---------------- aggregation + relu, emits bf16 hi/lo splits ---------------
__global__ __launch_bounds__(256, 4)
void k_agg(const float* __restrict__ h, const int* __restrict__ rowptr,
           const int* __restrict__ csr, const float* __restrict__ dinv,
           const float* __restrict__ bias, __nv_bfloat16* __restrict__ oh,
           __nv_bfloat16* __restrict__ ol) {
    int node = blockIdx.x * 4 + threadIdx.y;
    if (node >= NN) return;
    int c = threadIdx.x * 4;
    float di = dinv[node];
    float4 v = *(const float4*)(h + (size_t)node * HH + c);
    float w0 = di * di;
    float4 acc = make_float4(v.x*w0, v.y*w0, v.z*w0, v.w*w0);
    int lo = rowptr[node], hi = rowptr[node + 1];
    for (int e = lo; e < hi; e++) {
        int s = csr[e];
        float w = di * dinv[s];
        float4 u = *(const float4*)(h + (size_t)s * HH + c);
        acc.x += w*u.x; acc.y += w*u.y; acc.z += w*u.z; acc.w += w*u.w;
    }
    float4 b = *(const float4*)(bias + c);
    acc.x = fmaxf(acc.x + b.x, 0.f); acc.y = fmaxf(acc.y + b.y, 0.f);
    acc.z = fmaxf(acc.z + b.z, 0.f); acc.w = fmaxf(acc.w + b.w, 0.f);
    union { __nv_bfloat16 b[4]; uint2 u; } H, L;
    bsplit(acc.x, H.b[0], L.b[0]); bsplit(acc.y, H.b[1], L.b[1]);
    bsplit(acc.z, H.b[2], L.b[2]); bsplit(acc.w, H.b[3], L.b[3]);
    *(uint2*)(oh + (size_t)node * HH + c) = H.u;
    *(uint2*)(ol + (size_t)node * HH + c) = L.u;
}

// ---------------- pair epilogue ---------------------------------------------
__global__ __launch_bounds__(256)
void k_pair(const float* __restrict__ ZL, const float* __restrict__ ZR,
            const int* __restrict__ y, const float* __restrict__ fcb,
            const float* __restrict__ fc2W, const float* __restrict__ fc2b,
            float* __restrict__ out) {
    int w = threadIdx.x >> 5, lane = threadIdx.x & 31;
    int p = blockIdx.x * 8 + w;
    if (p >= PP) return;
    int y0 = y[2*p], y1 = y[2*p+1];
    int c = lane * 8;
    float s = 0.f;
    #pragma unroll
    for (int q = 0; q < 2; q++) {
        int cc = c + q * 4;
        float4 a = *(const float4*)(ZL + (size_t)y0 * HH + cc);
        float4 b = *(const float4*)(ZR + (size_t)y1 * HH + cc);
        float4 fb = *(const float4*)(fcb + cc);
        float4 fw = *(const float4*)(fc2W + cc);
        s += fmaxf(a.x + b.x + fb.x, 0.f) * fw.x;
        s += fmaxf(a.y + b.y + fb.y, 0.f) * fw.y;
        s += fmaxf(a.z + b.z + fb.z, 0.f) * fw.z;
        s += fmaxf(a.w + b.w + fb.w, 0.f) * fw.w;
    }
    #pragma unroll
    for (int o = 16; o > 0; o >>= 1) s += __shfl_xor_sync(~0u, s, o);
    if (lane == 0) out[p] = 1.f / (1.f + expf(-(s + fc2b[0])));
}

// ---------------- launch ----------------------------------------------------
extern "C" void kernel_launch(void* const* d_in, const int* in_sizes, int n_in,
                              void* d_out, int out_size) {
    const float* x_s  = (const float*)d_in[0];
    const float* x_t  = (const float*)d_in[1];
    const int*   ei_s = (const int*)  d_in[2];
    const int*   ei_t = (const int*)  d_in[3];
    const int*   y    = (const int*)  d_in[4];
    const float* W1   = (const float*)d_in[5];
    const float* b1   = (const float*)d_in[6];
    const float* W2   = (const float*)d_in[7];
    const float* b2   = (const float*)d_in[8];
    const float* fcW  = (const float*)d_in[9];
    const float* fcb  = (const float*)d_in[10];
    const float* fc2W = (const float*)d_in[11];
    const float* fc2b = (const float*)d_in[12];
    float* out = (float*)d_out;

    float *h, *ZL, *ZR, *dv;
    __nv_bfloat16 *Ah, *Al, *Bh, *Bl;
    int *deg, *rp, *wp, *cs, *bs, *bo;
    cudaGetSymbolAddress((void**)&h,  g_h);
    cudaGetSymbolAddress((void**)&Ah, g_Ah);
    cudaGetSymbolAddress((void**)&Al, g_Al);
    cudaGetSymbolAddress((void**)&ZL, g_ZL);
    cudaGetSymbolAddress((void**)&ZR, g_ZR);
    cudaGetSymbolAddress((void**)&Bh, g_Bh);
    cudaGetSymbolAddress((void**)&Bl, g_Bl);
    cudaGetSymbolAddress((void**)&dv, g_dinv);
    cudaGetSymbolAddress((void**)&deg, g_deg);
    cudaGetSymbolAddress((void**)&rp, g_rowptr);
    cudaGetSymbolAddress((void**)&wp, g_wptr);
    cudaGetSymbolAddress((void**)&cs, g_csr);
    cudaGetSymbolAddress((void**)&bs, g_bsum);
    cudaGetSymbolAddress((void**)&bo, g_boff);

    cudaFuncSetAttribute(k_gemm_bf, cudaFuncAttributeMaxDynamicSharedMemorySize, 81920);

    dim3 gn((NN + 255) / 256, 2), ge((EE + 255) / 256, 2);
    k_init_deg<<<gn, 256>>>(deg);
    k_count<<<ge, 256>>>(ei_s, ei_t, deg);
    k_dinv<<<gn, 256>>>(deg, dv);
    k_scan1<<<dim3(NSB, 2), 256>>>(deg, bs);
    k_scan2<<<dim3(1, 2), NSB>>>(bs, bo, rp);
    k_scan3<<<dim3(NSB, 2), 256>>>(deg, bo, rp, wp);
    k_fill<<<ge, 256>>>(ei_s, ei_t, wp, cs);

    // weight transpose+split: W1t@0 (32768), W2t@32768 (65536),
    // fcTop@98304 (65536), fcBot@163840 (65536)
    k_wsplit<<<dim3(DIN/32, HH/32), dim3(32,8)>>>(W1, Bh, Bl, DIN, HH);
    k_wsplit<<<dim3(HH/32, HH/32), dim3(32,8)>>>(W2, Bh + 32768, Bl + 32768, HH, HH);
    k_wsplit<<<dim3(HH/32, HH/32), dim3(32,8)>>>(fcW, Bh + 98304, Bl + 98304, HH, HH);
    k_wsplit<<<dim3(HH/32, HH/32), dim3(32,8)>>>(fcW + (size_t)HH * HH, Bh + 163840, Bl + 163840, HH, HH);

    dim3 gg((NN + 127) / 128, 2);
    int ag = (NN + 3) / 4;
    dim3 ab(64, 4);

    k_split_x<<<6250, 256>>>(x_s, Ah, Al, NN * DIN / 4);
    k_gemm_bf<<<gg, 256, 81920>>>(Ah, Al, Bh, Bl, h, NN, DIN);
    k_agg<<<ag, ab>>>(h, rp, cs, dv, b1, Ah, Al);
    k_gemm_bf<<<gg, 256, 81920>>>(Ah, Al, Bh + 32768, Bl + 32768, h, NN, HH);
    k_agg<<<ag, ab>>>(h, rp, cs, dv, b2, Ah, Al);
    k_gemm_bf<<<gg, 256, 81920>>>(Ah, Al, Bh + 98304, Bl + 98304, ZL, NN, HH);

    k_split_x<<<6250, 256>>>(x_t, Ah, Al, NN * DIN / 4);
    k_gemm_bf<<<gg, 256, 81920>>>(Ah, Al, Bh, Bl, h, NN, DIN);
    k_agg<<<ag, ab>>>(h, rp + NN + 1, cs + EE, dv + NN, b1, Ah, Al);
    k_gemm_bf<<<gg, 256, 81920>>>(Ah, Al, Bh + 32768, Bl + 32768, h, NN, HH);
    k_agg<<<ag, ab>>>(h, rp + NN + 1, cs + EE, dv + NN, b2, Ah, Al);
    k_gemm_bf<<<gg, 256, 81920>>>(Ah, Al, Bh + 163840, Bl + 163840, ZR, NN, HH);

    k_pair<<<(PP + 7) / 8, 256>>>(ZL, ZR, y, fcb, fc2W, fc2b, out);
}

// round 5
// speedup vs baseline: 3.1561x; 1.1621x over previous
#include <cuda_runtime.h>
#include <cuda_bf16.h>
#include <math.h>

#define NN 50000
#define EE 500000
#define DIN 128
#define HH 256
#define PP 100000
#define MR 50048           // padded per-side row stride (391*128)
#define MT (2*MR)          // 100096 total rows
#define NSB 128
#define CHUNK ((NN + NSB - 1) / NSB)
#define BST 40             // bf16 smem row stride (80B) -> conflict-free ldmatrix

__device__ float g_h [(size_t)MT*HH];          // fp32 intermediate / Z
__device__ __nv_bfloat16 g_Ah[(size_t)MT*HH];  // split pair P
__device__ __nv_bfloat16 g_Al[(size_t)MT*HH];
__device__ __nv_bfloat16 g_Ch[(size_t)MT*HH];  // split pair Q
__device__ __nv_bfloat16 g_Cl[(size_t)MT*HH];
__device__ __nv_bfloat16 g_Bh[229376];
__device__ __nv_bfloat16 g_Bl[229376];
__device__ int   g_deg[2*NN];
__device__ float g_dinv[2*NN];
__device__ int   g_rowptr[2*(NN+1)];
__device__ int   g_wptr[2*NN];
__device__ int   g_csr[2*EE];
__device__ int   g_bsum[2*NSB];
__device__ int   g_boff[2*NSB];

__device__ __forceinline__ void bsplit(float x, __nv_bfloat16& h, __nv_bfloat16& l) {
    h = __float2bfloat16_rn(x);
    l = __float2bfloat16_rn(x - __bfloat162float(h));
}

#define LDM4(R, A) asm volatile( \
    "ldmatrix.sync.aligned.m8n8.x4.shared.b16 {%0,%1,%2,%3}, [%4];" \
    : "=r"(R[0]),"=r"(R[1]),"=r"(R[2]),"=r"(R[3]) : "r"(A))
#define MMAB(D, A, B0, B1) asm volatile( \
    "mma.sync.aligned.m16n8k16.row.col.f32.bf16.bf16.f32 " \
    "{%0,%1,%2,%3},{%4,%5,%6,%7},{%8,%9},{%0,%1,%2,%3};" \
    : "+f"(D[0]),"+f"(D[1]),"+f"(D[2]),"+f"(D[3]) \
    : "r"(A[0]),"r"(A[1]),"r"(A[2]),"r"(A[3]),"r"(B0),"r"(B1))
#define CPA(D, S) asm volatile( \
    "cp.async.cg.shared.global [%0],[%1],16;" :: "r"(D),"l"(S))

// ---------------- CSR build (gridDim.y = side) ------------------------------
__global__ void k_init_deg(int* deg) {
    int i = blockIdx.x * blockDim.x + threadIdx.x;
    if (i < NN) deg[blockIdx.y * NN + i] = 1;
}
__global__ void k_count(const int* __restrict__ es, const int* __restrict__ et,
                        int* __restrict__ deg) {
    int e = blockIdx.x * blockDim.x + threadIdx.x;
    const int* ei = blockIdx.y ? et : es;
    if (e < EE) atomicAdd(&deg[blockIdx.y * NN + ei[EE + e]], 1);
}
__global__ void k_dinv(const int* __restrict__ deg, float* __restrict__ dinv) {
    int i = blockIdx.x * blockDim.x + threadIdx.x;
    if (i < NN) dinv[blockIdx.y * NN + i] = rsqrtf((float)deg[blockIdx.y * NN + i]);
}
__global__ void k_scan1(const int* __restrict__ deg, int* __restrict__ bsum) {
    const int* d = deg + blockIdx.y * NN;
    int lo = blockIdx.x * CHUNK, hi = min(lo + CHUNK, NN);
    int s = 0;
    for (int i = lo + threadIdx.x; i < hi; i += 256) s += d[i] - 1;
    __shared__ int sh[8];
    int lane = threadIdx.x & 31, w = threadIdx.x >> 5;
    #pragma unroll
    for (int o = 16; o > 0; o >>= 1) s += __shfl_down_sync(~0u, s, o);
    if (lane == 0) sh[w] = s;
    __syncthreads();
    if (threadIdx.x == 0) {
        int t = 0;
        #pragma unroll
        for (int j = 0; j < 8; j++) t += sh[j];
        bsum[blockIdx.y * NSB + blockIdx.x] = t;
    }
}
__global__ void k_scan2(const int* __restrict__ bsum, int* __restrict__ boff,
                        int* __restrict__ rowptr) {
    __shared__ int sb[NSB];
    int t = threadIdx.x, side = blockIdx.y;
    int orig = bsum[side * NSB + t];
    sb[t] = orig;
    __syncthreads();
    for (int o = 1; o < NSB; o <<= 1) {
        int v = (t >= o) ? sb[t - o] : 0;
        __syncthreads();
        sb[t] += v;
        __syncthreads();
    }
    boff[side * NSB + t] = sb[t] - orig;
    if (t == 0) rowptr[side * (NN + 1) + NN] = EE;
}
__global__ void k_scan3(const int* __restrict__ deg, const int* __restrict__ boff,
                        int* __restrict__ rowptr, int* __restrict__ wptr) {
    int side = blockIdx.y;
    const int* d = deg + side * NN;
    int* rp = rowptr + side * (NN + 1);
    int* wp = wptr + side * NN;
    int lo = blockIdx.x * CHUNK, hi = min(lo + CHUNK, NN);
    __shared__ int wsum[8];
    __shared__ int srun;
    if (threadIdx.x == 0) srun = boff[side * NSB + blockIdx.x];
    __syncthreads();
    int lane = threadIdx.x & 31, w = threadIdx.x >> 5;
    for (int t0 = lo; t0 < hi; t0 += 256) {
        int i = t0 + threadIdx.x;
        int v = (i < hi) ? d[i] - 1 : 0;
        int incl = v;
        #pragma unroll
        for (int o = 1; o < 32; o <<= 1) {
            int u = __shfl_up_sync(~0u, incl, o);
            if (lane >= o) incl += u;
        }
        if (lane == 31) wsum[w] = incl;
        __syncthreads();
        int woff = 0;
        for (int j = 0; j < w; j++) woff += wsum[j];
        if (i < hi) { int e = srun + woff + incl - v; rp[i] = e; wp[i] = e; }
        __syncthreads();
        if (threadIdx.x == 255) srun += woff + incl;
        __syncthreads();
    }
}
__global__ void k_fill(const int* __restrict__ es, const int* __restrict__ et,
                       int* __restrict__ wptr, int* __restrict__ csr) {
    int e = blockIdx.x * blockDim.x + threadIdx.x;
    const int* ei = blockIdx.y ? et : es;
    if (e < EE) {
        int p = atomicAdd(&wptr[blockIdx.y * NN + ei[EE + e]], 1);
        csr[blockIdx.y * EE + p] = ei[e];
    }
}

// transpose W[K,N] (row stride N) -> Bt[n*K + k], split bf16 hi/lo
__global__ void k_wsplit(const float* __restrict__ W, __nv_bfloat16* __restrict__ th,
                         __nv_bfloat16* __restrict__ tl, int K, int N) {
    __shared__ float sh[32][33];
    int k0 = blockIdx.x * 32, n0 = blockIdx.y * 32;
    int tx = threadIdx.x, ty = threadIdx.y;
    #pragma unroll
    for (int j = 0; j < 4; j++)
        sh[ty + j * 8][tx] = W[(size_t)(k0 + ty + j * 8) * N + n0 + tx];
    __syncthreads();
    #pragma unroll
    for (int j = 0; j < 4; j++) {
        int nn = ty + j * 8;
        float v = sh[tx][nn];
        __nv_bfloat16 h, l;
        bsplit(v, h, l);
        th[(size_t)(n0 + nn) * K + k0 + tx] = h;
        tl[(size_t)(n0 + nn) * K + k0 + tx] = l;
    }
}

// ---------------- agg0: splits of norm-agg of raw x (128 cols) --------------
__global__ __launch_bounds__(256, 4)
void k_aggx(const float* __restrict__ xs, const float* __restrict__ xt,
            const int* __restrict__ rowptr, const int* __restrict__ csr,
            const float* __restrict__ dinv,
            __nv_bfloat16* __restrict__ oh, __nv_bfloat16* __restrict__ ol) {
    int r = blockIdx.x * 8 + threadIdx.y;
    if (r >= MT) return;
    int side = r >= MR;
    int node = r - side * MR;
    int c = threadIdx.x * 4;
    union { __nv_bfloat16 b[4]; uint2 u; } H, L;
    if (node >= NN) {
        H.u = make_uint2(0, 0);
        *(uint2*)(oh + (size_t)r * DIN + c) = H.u;
        *(uint2*)(ol + (size_t)r * DIN + c) = H.u;
        return;
    }
    const float* x = side ? xt : xs;
    const float* dv = dinv + side * NN;
    const int* rp = rowptr + side * (NN + 1);
    const int* cs = csr + side * EE;
    float di = dv[node];
    float4 v = *(const float4*)(x + (size_t)node * DIN + c);
    float w0 = di * di;
    float4 acc = make_float4(v.x*w0, v.y*w0, v.z*w0, v.w*w0);
    int lo = rp[node], hi = rp[node + 1];
    for (int e = lo; e < hi; e++) {
        int s = cs[e];
        float w = di * dv[s];
        float4 u = *(const float4*)(x + (size_t)s * DIN + c);
        acc.x += w*u.x; acc.y += w*u.y; acc.z += w*u.z; acc.w += w*u.w;
    }
    bsplit(acc.x, H.b[0], L.b[0]); bsplit(acc.y, H.b[1], L.b[1]);
    bsplit(acc.z, H.b[2], L.b[2]); bsplit(acc.w, H.b[3], L.b[3]);
    *(uint2*)(oh + (size_t)r * DIN + c) = H.u;
    *(uint2*)(ol + (size_t)r * DIN + c) = L.u;
}

// ---------------- agg1: splits of norm-agg of h (256 cols) ------------------
__global__ __launch_bounds__(256, 4)
void k_aggh(const float* __restrict__ h, const int* __restrict__ rowptr,
            const int* __restrict__ csr, const float* __restrict__ dinv,
            __nv_bfloat16* __restrict__ oh, __nv_bfloat16* __restrict__ ol) {
    int r = blockIdx.x * 4 + threadIdx.y;
    if (r >= MT) return;
    int side = r >= MR;
    int node = r - side * MR;
    int c = threadIdx.x * 4;
    union { __nv_bfloat16 b[4]; uint2 u; } H, L;
    if (node >= NN) {
        H.u = make_uint2(0, 0);
        *(uint2*)(oh + (size_t)r * HH + c) = H.u;
        *(uint2*)(ol + (size_t)r * HH + c) = H.u;
        return;
    }
    const float* dv = dinv + side * NN;
    const int* rp = rowptr + side * (NN + 1);
    const int* cs = csr + side * EE;
    const float* hb = h + (size_t)side * MR * HH;
    float di = dv[node];
    float4 v = *(const float4*)(h + (size_t)r * HH + c);
    float w0 = di * di;
    float4 acc = make_float4(v.x*w0, v.y*w0, v.z*w0, v.w*w0);
    int lo = rp[node], hi = rp[node + 1];
    for (int e = lo; e < hi; e++) {
        int s = cs[e];
        float w = di * dv[s];
        float4 u = *(const float4*)(hb + (size_t)s * HH + c);
        acc.x += w*u.x; acc.y += w*u.y; acc.z += w*u.z; acc.w += w*u.w;
    }
    bsplit(acc.x, H.b[0], L.b[0]); bsplit(acc.y, H.b[1], L.b[1]);
    bsplit(acc.z, H.b[2], L.b[2]); bsplit(acc.w, H.b[3], L.b[3]);
    *(uint2*)(oh + (size_t)r * HH + c) = H.u;
    *(uint2*)(ol + (size_t)r * HH + c) = L.u;
}

// ---------------- bf16x3 tensor-core GEMM, fused epilogue -------------------
// MODE 0: relu(acc+bias) -> fp32 Cf;  MODE 1: relu(acc+bias) -> bsplit Oh/Ol;
// MODE 2: acc -> fp32 Cf, B chosen per side (B2 for rows >= MR).
template<int MODE>
__global__ __launch_bounds__(256)
void k_gemm_bf(const __nv_bfloat16* __restrict__ Ah, const __nv_bfloat16* __restrict__ Al,
               const __nv_bfloat16* __restrict__ Bth, const __nv_bfloat16* __restrict__ Btl,
               const __nv_bfloat16* __restrict__ B2h, const __nv_bfloat16* __restrict__ B2l,
               const float* __restrict__ bias, float* __restrict__ Cf,
               __nv_bfloat16* __restrict__ Oh, __nv_bfloat16* __restrict__ Ol, int K) {
    extern __shared__ __nv_bfloat16 smem_dyn[];
    unsigned smb = (unsigned)__cvta_generic_to_shared(smem_dyn);
    int tid = threadIdx.x, lane = tid & 31, wid = tid >> 5;
    int wm = wid & 1, wn = wid >> 1;
    int rb = blockIdx.x * 128, cb = blockIdx.y * 128;
    int T = K >> 5;
    const __nv_bfloat16* bh_src = (MODE == 2 && rb >= MR) ? B2h : Bth;
    const __nv_bfloat16* bl_src = (MODE == 2 && rb >= MR) ? B2l : Btl;

    float acc[4][4][4];
    #pragma unroll
    for (int a = 0; a < 4; a++)
        #pragma unroll
        for (int b = 0; b < 4; b++)
            #pragma unroll
            for (int c = 0; c < 4; c++) acc[a][b][c] = 0.f;

    int srow = tid >> 1, half = tid & 1;
    const __nv_bfloat16* pa = Ah + (size_t)(rb + srow) * K + half * 16;
    const __nv_bfloat16* pl = Al + (size_t)(rb + srow) * K + half * 16;
    const __nv_bfloat16* pb = bh_src + (size_t)(cb + srow) * K + half * 16;
    const __nv_bfloat16* pq = bl_src + (size_t)(cb + srow) * K + half * 16;
    unsigned sd = (unsigned)((srow * BST + half * 16) * 2);

    auto stage = [&](int t, int buf) {
        unsigned o = smb + buf * 10240 + sd;
        const __nv_bfloat16* a0 = pa + t * 32;
        CPA(o,         a0); CPA(o + 16,        a0 + 8);
        const __nv_bfloat16* a1 = pl + t * 32;
        CPA(o + 20480, a1); CPA(o + 20496,     a1 + 8);
        const __nv_bfloat16* b0 = pb + t * 32;
        CPA(o + 40960, b0); CPA(o + 40976,     b0 + 8);
        const __nv_bfloat16* b1 = pq + t * 32;
        CPA(o + 61440, b1); CPA(o + 61456,     b1 + 8);
    };

    stage(0, 0);
    asm volatile("cp.async.commit_group;");

    for (int t = 0; t < T; t++) {
        int buf = t & 1;
        if (t + 1 < T) {
            stage(t + 1, buf ^ 1);
            asm volatile("cp.async.commit_group;");
            asm volatile("cp.async.wait_group 1;");
        } else {
            asm volatile("cp.async.wait_group 0;");
        }
        __syncthreads();

        unsigned pAh = smb + buf * 10240;
        unsigned pAl = pAh + 20480;
        unsigned pBh = pAh + 40960;
        unsigned pBl = pAh + 61440;

        #pragma unroll
        for (int ks = 0; ks < 2; ks++) {
            unsigned ah[4][4], al[4][4], bh[2][4], bl[2][4];
            int ach = ks * 2 + (lane >> 4);
            int arow = wm * 64 + (lane & 15);
            #pragma unroll
            for (int mt = 0; mt < 4; mt++) {
                unsigned off = (unsigned)(((arow + mt * 16) * BST + ach * 8) * 2);
                LDM4(ah[mt], pAh + off);
                LDM4(al[mt], pAl + off);
            }
            int bch = ks * 2 + ((lane >> 3) & 1);
            int brow = wn * 32 + (lane & 7) + (lane >> 4) * 8;
            #pragma unroll
            for (int p = 0; p < 2; p++) {
                unsigned off = (unsigned)(((brow + p * 16) * BST + bch * 8) * 2);
                LDM4(bh[p], pBh + off);
                LDM4(bl[p], pBl + off);
            }
            #pragma unroll
            for (int mt = 0; mt < 4; mt++)
                #pragma unroll
                for (int nt = 0; nt < 4; nt++)
                    MMAB(acc[mt][nt], ah[mt], bh[nt >> 1][(nt & 1) * 2], bh[nt >> 1][(nt & 1) * 2 + 1]);
            #pragma unroll
            for (int mt = 0; mt < 4; mt++)
                #pragma unroll
                for (int nt = 0; nt < 4; nt++)
                    MMAB(acc[mt][nt], ah[mt], bl[nt >> 1][(nt & 1) * 2], bl[nt >> 1][(nt & 1) * 2 + 1]);
            #pragma unroll
            for (int mt = 0; mt < 4; mt++)
                #pragma unroll
                for (int nt = 0; nt < 4; nt++)
                    MMAB(acc[mt][nt], al[mt], bh[nt >> 1][(nt & 1) * 2], bh[nt >> 1][(nt & 1) * 2 + 1]);
        }
        __syncthreads();
    }

    int g = lane >> 2, tg = lane & 3;
    #pragma unroll
    for (int mt = 0; mt < 4; mt++) {
        int r0 = rb + wm * 64 + mt * 16 + g;
        #pragma unroll
        for (int nt = 0; nt < 4; nt++) {
            int c = cb + wn * 32 + nt * 8 + tg * 2;
            float2 bv = make_float2(0.f, 0.f);
            if (MODE < 2) bv = *(const float2*)(bias + c);
            #pragma unroll
            for (int hrow = 0; hrow < 2; hrow++) {
                int r = r0 + hrow * 8;
                float v0 = acc[mt][nt][hrow * 2];
                float v1 = acc[mt][nt][hrow * 2 + 1];
                if (MODE < 2) {
                    v0 = fmaxf(v0 + bv.x, 0.f);
                    v1 = fmaxf(v1 + bv.y, 0.f);
                }
                if (MODE == 1) {
                    __nv_bfloat16 h0, l0, h1, l1;
                    bsplit(v0, h0, l0); bsplit(v1, h1, l1);
                    *(__nv_bfloat162*)(Oh + (size_t)r * HH + c) = __nv_bfloat162(h0, h1);
                    *(__nv_bfloat162*)(Ol + (size_t)r * HH + c) = __nv_bfloat162(l0, l1);
                } else {
                    *(float2*)(Cf + (size_t)r * HH + c) = make_float2(v0, v1);
                }
            }
        }
    }
}

// ---------------- pair epilogue ---------------------------------------------
__global__ __launch_bounds__(256)
void k_pair(const float* __restrict__ Z, const int* __restrict__ y,
            const float* __restrict__ fcb, const float* __restrict__ fc2W,
            const float* __restrict__ fc2b, float* __restrict__ out) {
    int w = threadIdx.x >> 5, lane = threadIdx.x & 31;
    int p = blockIdx.x * 8 + w;
    if (p >= PP) return;
    int y0 = y[2*p], y1 = y[2*p+1];
    const float* zl = Z + (size_t)y0 * HH;
    const float* zr = Z + (size_t)(MR + y1) * HH;
    int c = lane * 8;
    float s = 0.f;
    #pragma unroll
    for (int q = 0; q < 2; q++) {
        int cc = c + q * 4;
        float4 a = *(const float4*)(zl + cc);
        float4 b = *(const float4*)(zr + cc);
        float4 fb = *(const float4*)(fcb + cc);
        float4 fw = *(const float4*)(fc2W + cc);
        s += fmaxf(a.x + b.x + fb.x, 0.f) * fw.x;
        s += fmaxf(a.y + b.y + fb.y, 0.f) * fw.y;
        s += fmaxf(a.z + b.z + fb.z, 0.f) * fw.z;
        s += fmaxf(a.w + b.w + fb.w, 0.f) * fw.w;
    }
    #pragma unroll
    for (int o = 16; o > 0; o >>= 1) s += __shfl_xor_sync(~0u, s, o);
    if (lane == 0) out[p] = 1.f / (1.f + expf(-(s + fc2b[0])));
}

// ---------------- launch ----------------------------------------------------
extern "C" void kernel_launch(void* const* d_in, const int* in_sizes, int n_in,
                              void* d_out, int out_size) {
    const float* x_s  = (const float*)d_in[0];
    const float* x_t  = (const float*)d_in[1];
    const int*   ei_s = (const int*)  d_in[2];
    const int*   ei_t = (const int*)  d_in[3];
    const int*   y    = (const int*)  d_in[4];
    const float* W1   = (const float*)d_in[5];
    const float* b1   = (const float*)d_in[6];
    const float* W2   = (const float*)d_in[7];
    const float* b2   = (const float*)d_in[8];
    const float* fcW  = (const float*)d_in[9];
    const float* fcb  = (const float*)d_in[10];
    const float* fc2W = (const float*)d_in[11];
    const float* fc2b = (const float*)d_in[12];
    float* out = (float*)d_out;

    float *h, *dv;
    __nv_bfloat16 *Ah, *Al, *Ch, *Cl, *Bh, *Bl;
    int *deg, *rp, *wp, *cs, *bs, *bo;
    cudaGetSymbolAddress((void**)&h,  g_h);
    cudaGetSymbolAddress((void**)&Ah, g_Ah);
    cudaGetSymbolAddress((void**)&Al, g_Al);
    cudaGetSymbolAddress((void**)&Ch, g_Ch);
    cudaGetSymbolAddress((void**)&Cl, g_Cl);
    cudaGetSymbolAddress((void**)&Bh, g_Bh);
    cudaGetSymbolAddress((void**)&Bl, g_Bl);
    cudaGetSymbolAddress((void**)&dv, g_dinv);
    cudaGetSymbolAddress((void**)&deg, g_deg);
    cudaGetSymbolAddress((void**)&rp, g_rowptr);
    cudaGetSymbolAddress((void**)&wp, g_wptr);
    cudaGetSymbolAddress((void**)&cs, g_csr);
    cudaGetSymbolAddress((void**)&bs, g_bsum);
    cudaGetSymbolAddress((void**)&bo, g_boff);

    cudaFuncSetAttribute(k_gemm_bf<0>, cudaFuncAttributeMaxDynamicSharedMemorySize, 81920);
    cudaFuncSetAttribute(k_gemm_bf<1>, cudaFuncAttributeMaxDynamicSharedMemorySize, 81920);
    cudaFuncSetAttribute(k_gemm_bf<2>, cudaFuncAttributeMaxDynamicSharedMemorySize, 81920);

    // weights: W1t@0, W2t@32768, fcTop@98304, fcBot@163840
    k_wsplit<<<dim3(DIN/32, HH/32), dim3(32,8)>>>(W1, Bh, Bl, DIN, HH);
    k_wsplit<<<dim3(HH/32, HH/32), dim3(32,8)>>>(W2, Bh + 32768, Bl + 32768, HH, HH);
    k_wsplit<<<dim3(HH/32, HH/32), dim3(32,8)>>>(fcW, Bh + 98304, Bl + 98304, HH, HH);
    k_wsplit<<<dim3(HH/32, HH/32), dim3(32,8)>>>(fcW + (size_t)HH * HH, Bh + 163840, Bl + 163840, HH, HH);

    dim3 gn((NN + 255) / 256, 2), ge((EE + 255) / 256, 2);
    k_init_deg<<<gn, 256>>>(deg);
    k_count<<<ge, 256>>>(ei_s, ei_t, deg);
    k_dinv<<<gn, 256>>>(deg, dv);
    k_scan1<<<dim3(NSB, 2), 256>>>(deg, bs);
    k_scan2<<<dim3(1, 2), NSB>>>(bs, bo, rp);
    k_scan3<<<dim3(NSB, 2), 256>>>(deg, bo, rp, wp);
    k_fill<<<ge, 256>>>(ei_s, ei_t, wp, cs);

    dim3 gg(MT / 128, 2);
    k_aggx<<<MT / 8, dim3(32, 8)>>>(x_s, x_t, rp, cs, dv, Ah, Al);
    k_gemm_bf<0><<<gg, 256, 81920>>>(Ah, Al, Bh, Bl, Bh, Bl, b1, h, Ah, Al, DIN);
    k_aggh<<<MT / 4, dim3(64, 4)>>>(h, rp, cs, dv, Ch, Cl);
    k_gemm_bf<1><<<gg, 256, 81920>>>(Ch, Cl, Bh + 32768, Bl + 32768, Bh, Bl, b2, h, Ah, Al, HH);
    k_gemm_bf<2><<<gg, 256, 81920>>>(Ah, Al, Bh + 98304, Bl + 98304, Bh + 163840, Bl + 163840,
                                     b2, h, Ah, Al, HH);
    k_pair<<<(PP + 7) / 8, 256>>>(h, y, fcb, fc2W, fc2b, out);
}